// round 1
// baseline (speedup 1.0000x reference)
#include <cuda_runtime.h>
#include <cstdint>

// Problem constants
#define LAY 2
#define BB  32
#define TT  256
#define NN  1024
#define MM  1024
#define G4  4096
#define RR  (BB*TT)          // 8192 rows of the hoisted input GEMM

// ---------------- device scratch (static: no allocation allowed) -------------
__device__ float g_G[(size_t)RR * G4];        // input-projection gates, 134 MB
__device__ float g_H0[(size_t)RR * MM];       // layer-0 h sequence, 33.5 MB
__device__ float g_WhhT[(size_t)LAY * MM * G4]; // transposed recurrent weights
__device__ float g_bsum[LAY * G4];
__device__ float g_h[BB * MM];
__device__ float g_c[BB * MM];
__device__ float g_gates[BB * G4];
__device__ unsigned g_bar_cnt = 0;
__device__ unsigned g_bar_gen = 0;

// ---------------- packed fp32x2 helpers (B300 FFMA2 pipe) --------------------
__device__ __forceinline__ unsigned long long pack_dup(float a) {
    unsigned long long d;
    unsigned u = __float_as_uint(a);
    asm("mov.b64 %0, {%1, %1};" : "=l"(d) : "r"(u));
    return d;
}
__device__ __forceinline__ void fma2(unsigned long long& acc,
                                     unsigned long long a, unsigned long long b) {
    asm("fma.rn.f32x2 %0, %1, %2, %0;" : "+l"(acc) : "l"(a), "l"(b));
}
__device__ __forceinline__ float2 unpack2(unsigned long long d) {
    unsigned lo, hi;
    asm("mov.b64 {%0, %1}, %2;" : "=r"(lo), "=r"(hi) : "l"(d));
    return make_float2(__uint_as_float(lo), __uint_as_float(hi));
}

__device__ __forceinline__ float fast_sigmoid(float x) {
    return 1.0f / (1.0f + __expf(-x));
}
__device__ __forceinline__ float fast_tanh(float x) {
    // 2*sigmoid(2x)-1 ; saturates correctly for |x| large
    return 2.0f / (1.0f + __expf(-2.0f * x)) - 1.0f;
}

// ---------------- grid-wide barrier (128 blocks, all wave-1 resident) --------
__device__ __forceinline__ void grid_barrier(unsigned nblk) {
    __syncthreads();
    if (threadIdx.x == 0) {
        __threadfence();
        unsigned gen = *(volatile unsigned*)&g_bar_gen;
        if (atomicAdd(&g_bar_cnt, 1u) == nblk - 1) {
            g_bar_cnt = 0;
            __threadfence();
            *(volatile unsigned*)&g_bar_gen = gen + 1;
        } else {
            while (*(volatile unsigned*)&g_bar_gen == gen) { __nanosleep(32); }
        }
        __threadfence();
    }
    __syncthreads();
}

// ---------------- prep: bsum = bih+bhh ; WhhT[l][k][j] = Whh[l][j][k] --------
__global__ void prep_kernel(const float* __restrict__ Whh,
                            const float* __restrict__ bih,
                            const float* __restrict__ bhh) {
    size_t idx = (size_t)blockIdx.x * blockDim.x + threadIdx.x;
    size_t total = (size_t)LAY * G4 * MM;
    if (idx < total) {
        size_t l   = idx / ((size_t)G4 * MM);
        size_t rem = idx % ((size_t)G4 * MM);
        size_t j = rem / MM, k = rem % MM;
        g_WhhT[l * ((size_t)MM * G4) + k * G4 + j] = Whh[idx];
    }
    if (idx < (size_t)LAY * G4) g_bsum[idx] = bih[idx] + bhh[idx];
}

// ---------------- big input GEMM: C[r][j] = sum_k A[r][k]*W[j][k] ------------
// A: (8192 x 1024) row-major, W: (4096 x 1024) row-major, C = g_G.
// 128x128 block tile, 256 threads, 8x8 per thread via packed f32x2.
__global__ __launch_bounds__(256) void gemm_kernel(int layer,
                                                   const float* __restrict__ X,
                                                   const float* __restrict__ Wih) {
    const float* A = layer ? g_H0 : X;
    const float* W = Wih + (size_t)layer * G4 * NN;
    float* C = g_G;

    __shared__ float As[8][128];
    __shared__ float Ws[8][128];

    int tid = threadIdx.x;
    int j0 = blockIdx.x * 128, r0 = blockIdx.y * 128;
    int tx = tid & 15, ty = tid >> 4;
    int lr = tid >> 1, lk = (tid & 1) * 4;

    unsigned long long acc[8][4];
#pragma unroll
    for (int i = 0; i < 8; i++)
#pragma unroll
        for (int j = 0; j < 4; j++) acc[i][j] = 0ULL;

    for (int kt = 0; kt < NN; kt += 8) {
        float4 av = *(const float4*)&A[(size_t)(r0 + lr) * NN + kt + lk];
        float4 wv = *(const float4*)&W[(size_t)(j0 + lr) * NN + kt + lk];
        __syncthreads();
        As[lk + 0][lr] = av.x; As[lk + 1][lr] = av.y;
        As[lk + 2][lr] = av.z; As[lk + 3][lr] = av.w;
        Ws[lk + 0][lr] = wv.x; Ws[lk + 1][lr] = wv.y;
        Ws[lk + 2][lr] = wv.z; Ws[lk + 3][lr] = wv.w;
        __syncthreads();
#pragma unroll
        for (int kk = 0; kk < 8; kk++) {
            float4 a0 = *(float4*)&As[kk][ty * 8];
            float4 a1 = *(float4*)&As[kk][ty * 8 + 4];
            unsigned long long w[4];
            w[0] = *(unsigned long long*)&Ws[kk][tx * 8 + 0];
            w[1] = *(unsigned long long*)&Ws[kk][tx * 8 + 2];
            w[2] = *(unsigned long long*)&Ws[kk][tx * 8 + 4];
            w[3] = *(unsigned long long*)&Ws[kk][tx * 8 + 6];
            unsigned long long ad[8];
            ad[0] = pack_dup(a0.x); ad[1] = pack_dup(a0.y);
            ad[2] = pack_dup(a0.z); ad[3] = pack_dup(a0.w);
            ad[4] = pack_dup(a1.x); ad[5] = pack_dup(a1.y);
            ad[6] = pack_dup(a1.z); ad[7] = pack_dup(a1.w);
#pragma unroll
            for (int bi = 0; bi < 8; bi++)
#pragma unroll
                for (int ji = 0; ji < 4; ji++) fma2(acc[bi][ji], ad[bi], w[ji]);
        }
    }

#pragma unroll
    for (int bi = 0; bi < 8; bi++) {
        size_t row = (size_t)(r0 + ty * 8 + bi);
#pragma unroll
        for (int ji = 0; ji < 4; ji++) {
            float2 v = unpack2(acc[bi][ji]);
            *(float2*)&C[row * G4 + j0 + tx * 8 + ji * 2] = v;
        }
    }
}

// ---------------- persistent recurrence kernel (one layer, all 256 steps) ----
// 128 blocks x 256 threads. Per step:
//  phase 1: gates[b][j] = h . WhhT[:,j]  (+ G + bias)  — block owns 32 j cols,
//           split-K across two 128-thread halves, f32x2 inner.
//  phase 2: pointwise LSTM cell update, one (b,m) element per thread.
__global__ __launch_bounds__(256) void recur_kernel(int layer,
                                                    const float* __restrict__ hin,
                                                    const float* __restrict__ cin,
                                                    float* __restrict__ dout) {
    const unsigned NB = 128;
    const float* Gm = g_G;
    const float* Wt = g_WhhT + (size_t)layer * MM * G4;
    const float* bs = g_bsum + layer * G4;
    float* outseq = layer ? dout : g_H0;
    float* hf = dout + (size_t)RR * MM + (size_t)layer * BB * MM;
    float* cf = dout + (size_t)RR * MM + (size_t)LAY * BB * MM + (size_t)layer * BB * MM;

    int tid = threadIdx.x;
    int bid = blockIdx.x;

    // init running state from inputs
    {
        int g = bid * 256 + tid;   // 0..32767
        g_h[g] = hin[(size_t)layer * BB * MM + g];
        g_c[g] = cin[(size_t)layer * BB * MM + g];
    }
    grid_barrier(NB);

    __shared__ float hs[2][32][33];
    __shared__ float ws[2][32][32];
    __shared__ unsigned long long red[128][4];

    int sub = tid >> 7;          // split-K half
    int r = tid & 127;
    int jl = (r & 7) * 4;        // 4 consecutive j per thread
    int b0 = (r >> 3) * 2;       // 2 consecutive b per thread
    int j0 = bid * 32;
    int kkh = r & 31;            // lane's k index within a tile (for loads)
    int lq = r >> 5;

    for (int t = 0; t < TT; t++) {
        // ---------------- phase 1: gate GEMM ----------------
        unsigned long long acc0 = 0, acc1 = 0, acc2 = 0, acc3 = 0;
        int kbase = sub * 512;
        for (int kt = 0; kt < 512; kt += 32) {
            int k0 = kbase + kt;
#pragma unroll
            for (int i = 0; i < 8; i++) {
                int q = lq + i * 4;                       // h row (batch)
                hs[sub][kkh][q] = g_h[q * MM + k0 + kkh];
                int kk2 = lq + i * 4;                     // w k-row
                ws[sub][kk2][kkh] = Wt[(size_t)(k0 + kk2) * G4 + j0 + kkh];
            }
            __syncthreads();
#pragma unroll
            for (int kk = 0; kk < 32; kk++) {
                float a0 = hs[sub][kk][b0];
                float a1 = hs[sub][kk][b0 + 1];
                unsigned long long w01 = *(const unsigned long long*)&ws[sub][kk][jl];
                unsigned long long w23 = *(const unsigned long long*)&ws[sub][kk][jl + 2];
                unsigned long long a0d = pack_dup(a0);
                unsigned long long a1d = pack_dup(a1);
                fma2(acc0, a0d, w01); fma2(acc1, a0d, w23);
                fma2(acc2, a1d, w01); fma2(acc3, a1d, w23);
            }
            __syncthreads();
        }
        if (sub == 1) {
            red[r][0] = acc0; red[r][1] = acc1; red[r][2] = acc2; red[r][3] = acc3;
        }
        __syncthreads();
        if (sub == 0) {
            float2 p0 = unpack2(acc0), q0 = unpack2(red[r][0]);
            float2 p1 = unpack2(acc1), q1 = unpack2(red[r][1]);
            float2 p2 = unpack2(acc2), q2 = unpack2(red[r][2]);
            float2 p3 = unpack2(acc3), q3 = unpack2(red[r][3]);
            float v[2][4];
            v[0][0] = p0.x + q0.x; v[0][1] = p0.y + q0.y;
            v[0][2] = p1.x + q1.x; v[0][3] = p1.y + q1.y;
            v[1][0] = p2.x + q2.x; v[1][1] = p2.y + q2.y;
            v[1][2] = p3.x + q3.x; v[1][3] = p3.y + q3.y;
#pragma unroll
            for (int bi = 0; bi < 2; bi++) {
                int b = b0 + bi;
                const float* Grow = Gm + ((size_t)b * TT + t) * G4 + j0;
#pragma unroll
                for (int jj = 0; jj < 4; jj++) {
                    int jc = jl + jj;
                    g_gates[b * G4 + j0 + jc] = v[bi][jj] + Grow[jc] + bs[j0 + jc];
                }
            }
        }
        grid_barrier(NB);

        // ---------------- phase 2: pointwise cell update ----------------
        {
            int g = bid * 256 + tid;     // 0..32767
            int b = g >> 10, m = g & 1023;
            float gi = g_gates[b * G4 + m];
            float gf = g_gates[b * G4 + m + 1024];
            float gg = g_gates[b * G4 + m + 2048];
            float go = g_gates[b * G4 + m + 3072];
            float cprev = g_c[g];
            float iv = fast_sigmoid(gi);
            float fv = fast_sigmoid(gf);
            float ov = fast_sigmoid(go);
            float gv = fast_tanh(gg);
            float cn = fv * cprev + iv * gv;
            float hn = ov * fast_tanh(cn);
            g_c[g] = cn;
            g_h[g] = hn;
            outseq[((size_t)b * TT + t) * MM + m] = hn;
            if (t == TT - 1) { hf[g] = hn; cf[g] = cn; }
        }
        grid_barrier(NB);
    }
}

// ---------------------------- launch ----------------------------------------
extern "C" void kernel_launch(void* const* d_in, const int* in_sizes, int n_in,
                              void* d_out, int out_size) {
    const float* x   = (const float*)d_in[0];
    const float* h   = (const float*)d_in[1];
    const float* c   = (const float*)d_in[2];
    const float* Wih = (const float*)d_in[3];
    const float* Whh = (const float*)d_in[4];
    const float* bih = (const float*)d_in[5];
    const float* bhh = (const float*)d_in[6];
    float* out = (float*)d_out;

    size_t prep_total = (size_t)LAY * G4 * MM;
    prep_kernel<<<(unsigned)((prep_total + 255) / 256), 256>>>(Whh, bih, bhh);

    for (int l = 0; l < LAY; l++) {
        gemm_kernel<<<dim3(G4 / 128, RR / 128), 256>>>(l, x, Wih);
        recur_kernel<<<128, 256>>>(l, h, c, out);
    }
}

// round 4
// speedup vs baseline: 3.2181x; 3.2181x over previous
#include <cuda_runtime.h>
#include <cuda_bf16.h>
#include <cstdint>

#define LAY 2
#define BB  32
#define TT  256
#define NN  1024
#define MM  1024
#define G4  4096
#define RR  (BB*TT)

// ---------------- device scratch (no allocation allowed) ---------------------
__device__ float g_G[(size_t)RR * G4];                       // input-proj gates
__device__ __align__(16) __nv_bfloat16 g_Xhi[(size_t)RR*NN];
__device__ __align__(16) __nv_bfloat16 g_Xlo[(size_t)RR*NN];
__device__ __align__(16) __nv_bfloat16 g_H0hi[(size_t)RR*MM];
__device__ __align__(16) __nv_bfloat16 g_H0lo[(size_t)RR*MM];
__device__ __align__(16) __nv_bfloat16 g_Wihhi[(size_t)LAY*G4*NN];
__device__ __align__(16) __nv_bfloat16 g_Wihlo[(size_t)LAY*G4*NN];
__device__ __align__(16) __nv_bfloat16 g_Whhhi[(size_t)LAY*G4*MM];
__device__ __align__(16) __nv_bfloat16 g_Whhlo[(size_t)LAY*G4*MM];
__device__ __align__(16) __nv_bfloat16 g_hbhi[BB*MM];
__device__ __align__(16) __nv_bfloat16 g_hblo[BB*MM];
__device__ float g_c[BB*MM];
__device__ float g_part[(size_t)4*BB*G4];     // [ks*32+b][j]
__device__ float g_bsum[LAY*G4];
__device__ unsigned g_bar_cnt = 0;
__device__ unsigned g_bar_gen = 0;

// ---------------- helpers ----------------------------------------------------
__device__ __forceinline__ void mma16816(float* c, const uint32_t* a, const uint32_t* b) {
    asm("mma.sync.aligned.m16n8k16.row.col.f32.bf16.bf16.f32 "
        "{%0,%1,%2,%3}, {%4,%5,%6,%7}, {%8,%9}, {%0,%1,%2,%3};"
        : "+f"(c[0]), "+f"(c[1]), "+f"(c[2]), "+f"(c[3])
        : "r"(a[0]), "r"(a[1]), "r"(a[2]), "r"(a[3]), "r"(b[0]), "r"(b[1]));
}
__device__ __forceinline__ void cp16(void* dst, const void* src) {
    uint32_t d = (uint32_t)__cvta_generic_to_shared(dst);
    asm volatile("cp.async.cg.shared.global [%0], [%1], 16;" :: "r"(d), "l"(src));
}
#define CP_COMMIT()  asm volatile("cp.async.commit_group;" ::: "memory")
#define CP_WAIT(n)   asm volatile("cp.async.wait_group %0;" :: "n"(n) : "memory")

__device__ __forceinline__ float fast_sigmoid(float x) { return 1.0f / (1.0f + __expf(-x)); }
__device__ __forceinline__ float fast_tanh(float x)    { return 2.0f / (1.0f + __expf(-2.0f * x)) - 1.0f; }

// ---------------- grid barrier (proven in round 1) ---------------------------
__device__ __forceinline__ void grid_barrier(unsigned nblk) {
    __threadfence();
    __syncthreads();
    if (threadIdx.x == 0) {
        unsigned gen = *(volatile unsigned*)&g_bar_gen;
        if (atomicAdd(&g_bar_cnt, 1u) == nblk - 1) {
            g_bar_cnt = 0;
            __threadfence();
            *(volatile unsigned*)&g_bar_gen = gen + 1;
        } else {
            while (*(volatile unsigned*)&g_bar_gen == gen) { __nanosleep(20); }
        }
        __threadfence();
    }
    __syncthreads();
}

// ---------------- prep: bf16 hi/lo splits + bias sum -------------------------
__global__ void prep_kernel(const float* __restrict__ x,
                            const float* __restrict__ Wih,
                            const float* __restrict__ Whh,
                            const float* __restrict__ bih,
                            const float* __restrict__ bhh) {
    size_t i = (size_t)blockIdx.x * 256 + threadIdx.x;   // 8,388,608 total
    {
        float v = x[i];
        __nv_bfloat16 hi = __float2bfloat16(v);
        g_Xhi[i] = hi;
        g_Xlo[i] = __float2bfloat16(v - __bfloat162float(hi));
    }
    {
        float v = Wih[i];
        __nv_bfloat16 hi = __float2bfloat16(v);
        g_Wihhi[i] = hi;
        g_Wihlo[i] = __float2bfloat16(v - __bfloat162float(hi));
    }
    {
        float v = Whh[i];
        __nv_bfloat16 hi = __float2bfloat16(v);
        g_Whhhi[i] = hi;
        g_Whhlo[i] = __float2bfloat16(v - __bfloat162float(hi));
    }
    if (i < (size_t)LAY * G4) g_bsum[i] = bih[i] + bhh[i];
}

// =================== input GEMM: G[r][j] = act[r] . Wih[j] ===================
// 128x128 tile, K=1024, 2-stage cp.async, bf16 HMMA, 3-pass hi/lo.
// smem per stage: 4 tiles of [128][40] bf16 (pad 40 -> conflict-free frags)
#define IGO_WHI 0
#define IGO_WLO 10240
#define IGO_AHI 20480
#define IGO_ALO 30720
#define IG_STAGE 40960
#define IG_SMEM (2*IG_STAGE)

__device__ __forceinline__ void ig_load(char* sm, int stage,
                                        const __nv_bfloat16* Whi, const __nv_bfloat16* Wlo,
                                        const __nv_bfloat16* Ahi, const __nv_bfloat16* Alo,
                                        int j0, int r0, int kc, int tid) {
    char* s = sm + stage * IG_STAGE;
#pragma unroll
    for (int i = 0; i < 2; i++) {
        int idx = i * 256 + tid;
        int row = idx >> 2, q = idx & 3;
        int so = row * 80 + q * 16;
        size_t wsrc = (size_t)(j0 + row) * NN + kc + q * 8;
        size_t asrc = (size_t)(r0 + row) * NN + kc + q * 8;
        cp16(s + IGO_WHI + so, Whi + wsrc);
        cp16(s + IGO_WLO + so, Wlo + wsrc);
        cp16(s + IGO_AHI + so, Ahi + asrc);
        cp16(s + IGO_ALO + so, Alo + asrc);
    }
}

__global__ __launch_bounds__(256, 1)
void igemm_kernel(int layer, int useH0) {
    extern __shared__ char sm[];
    int tid = threadIdx.x, w = tid >> 5, lane = tid & 31;
    int g = lane >> 2, tg = lane & 3;
    int wm = w >> 2, wn = w & 3;            // warp tile: 64(m) x 32(n)
    int r0 = blockIdx.x * 128;              // activation rows (N side)
    int j0 = blockIdx.y * 128;              // gate rows (M side)

    const __nv_bfloat16* Whi = g_Wihhi + (size_t)layer * G4 * NN;
    const __nv_bfloat16* Wlo = g_Wihlo + (size_t)layer * G4 * NN;
    const __nv_bfloat16* Ahi = useH0 ? g_H0hi : g_Xhi;
    const __nv_bfloat16* Alo = useH0 ? g_H0lo : g_Xlo;

    float acc[4][4][4];
#pragma unroll
    for (int a = 0; a < 4; a++)
#pragma unroll
        for (int b = 0; b < 4; b++)
#pragma unroll
            for (int e = 0; e < 4; e++) acc[a][b][e] = 0.f;

    ig_load(sm, 0, Whi, Wlo, Ahi, Alo, j0, r0, 0, tid);
    CP_COMMIT();

    for (int c = 0; c < 32; c++) {
        if (c + 1 < 32) {
            ig_load(sm, (c + 1) & 1, Whi, Wlo, Ahi, Alo, j0, r0, (c + 1) * 32, tid);
            CP_COMMIT();
            CP_WAIT(1);
        } else {
            CP_WAIT(0);
        }
        __syncthreads();
        const char* st = sm + (c & 1) * IG_STAGE;
#pragma unroll
        for (int k16 = 0; k16 < 2; k16++) {
            int kb = k16 * 32 + 4 * tg;     // byte offset in row
            uint32_t ah[4][4], al[4][4];
#pragma unroll
            for (int mt = 0; mt < 4; mt++) {
                int rb = (wm * 64 + mt * 16 + g) * 80 + kb;
                ah[mt][0] = *(const uint32_t*)(st + IGO_WHI + rb);
                ah[mt][1] = *(const uint32_t*)(st + IGO_WHI + rb + 8 * 80);
                ah[mt][2] = *(const uint32_t*)(st + IGO_WHI + rb + 16);
                ah[mt][3] = *(const uint32_t*)(st + IGO_WHI + rb + 8 * 80 + 16);
                al[mt][0] = *(const uint32_t*)(st + IGO_WLO + rb);
                al[mt][1] = *(const uint32_t*)(st + IGO_WLO + rb + 8 * 80);
                al[mt][2] = *(const uint32_t*)(st + IGO_WLO + rb + 16);
                al[mt][3] = *(const uint32_t*)(st + IGO_WLO + rb + 8 * 80 + 16);
            }
            uint32_t bh[4][2], bl[4][2];
#pragma unroll
            for (int nt = 0; nt < 4; nt++) {
                int rb = (wn * 32 + nt * 8 + g) * 80 + kb;
                bh[nt][0] = *(const uint32_t*)(st + IGO_AHI + rb);
                bh[nt][1] = *(const uint32_t*)(st + IGO_AHI + rb + 16);
                bl[nt][0] = *(const uint32_t*)(st + IGO_ALO + rb);
                bl[nt][1] = *(const uint32_t*)(st + IGO_ALO + rb + 16);
            }
#pragma unroll
            for (int mt = 0; mt < 4; mt++)
#pragma unroll
                for (int nt = 0; nt < 4; nt++) {
                    mma16816(acc[mt][nt], ah[mt], bh[nt]);
                    mma16816(acc[mt][nt], ah[mt], bl[nt]);
                    mma16816(acc[mt][nt], al[mt], bh[nt]);
                }
        }
        __syncthreads();
    }

    // epilogue: D[m=j][n=r] -> g_G[r][j]
#pragma unroll
    for (int mt = 0; mt < 4; mt++)
#pragma unroll
        for (int nt = 0; nt < 4; nt++) {
            int m = j0 + wm * 64 + mt * 16 + g;
            int n = r0 + wn * 32 + nt * 8 + 2 * tg;
            g_G[(size_t)n * G4 + m]           = acc[mt][nt][0];
            g_G[(size_t)(n + 1) * G4 + m]     = acc[mt][nt][1];
            g_G[(size_t)n * G4 + m + 8]       = acc[mt][nt][2];
            g_G[(size_t)(n + 1) * G4 + m + 8] = acc[mt][nt][3];
        }
}

// =================== persistent recurrence kernel ============================
// 128 CTAs = 32 mtiles x 4 ksplits. Weight frags live in REGISTERS.
// smem: h tiles [32][280] bf16 hi+lo (stride 280 -> conflict-free B-frags)
//       + weight staging [128][280] bf16 hi+lo (one-time)
#define RO_HHI 0
#define RO_HLO 17920
#define RO_WHI 35840
#define RO_WLO 107520
#define RC_SMEM 179200

__global__ __launch_bounds__(256, 1)
void recur_kernel(int layer, const float* __restrict__ h_in,
                  const float* __restrict__ c_in, float* __restrict__ dout) {
    extern __shared__ char sm[];
    const unsigned NB = 128;
    int tid = threadIdx.x, w = tid >> 5, lane = tid & 31, bid = blockIdx.x;
    int g = lane >> 2, tg = lane & 3;
    int mtile = bid >> 2, ks = bid & 3;
    int j0 = mtile * 128, k0 = ks * 256;

    const __nv_bfloat16* Whi = g_Whhhi + (size_t)layer * G4 * MM;
    const __nv_bfloat16* Wlo = g_Whhlo + (size_t)layer * G4 * MM;
    const float* bs  = g_bsum + layer * G4;
    const float* hin = h_in + (size_t)layer * BB * MM;
    const float* cin = c_in + (size_t)layer * BB * MM;
    float* hf = dout + (size_t)RR * MM + (size_t)layer * BB * MM;
    float* cf = dout + (size_t)RR * MM + (size_t)LAY * BB * MM + (size_t)layer * BB * MM;

    // ---- init running state (each CTA owns 256 elems) ----
    {
        int gi = bid * 256 + tid;
        float hv = hin[gi];
        __nv_bfloat16 hhi = __float2bfloat16(hv);
        g_hbhi[gi] = hhi;
        g_hblo[gi] = __float2bfloat16(hv - __bfloat162float(hhi));
        g_c[gi] = cin[gi];
    }

    // ---- one-time: stage weight slice, load frags into registers ----
    uint32_t whi[16][4], wlo[16][4];
    {
#pragma unroll
        for (int i = 0; i < 16; i++) {
            int idx = i * 256 + tid;
            int row = idx >> 5, q = idx & 31;
            size_t src = (size_t)(j0 + row) * MM + k0 + q * 8;
            *(uint4*)(sm + RO_WHI + row * 560 + q * 16) = *(const uint4*)(Whi + src);
            *(uint4*)(sm + RO_WLO + row * 560 + q * 16) = *(const uint4*)(Wlo + src);
        }
        __syncthreads();
#pragma unroll
        for (int kt = 0; kt < 16; kt++) {
            int rb = (w * 16 + g) * 560 + kt * 32 + 4 * tg;
            whi[kt][0] = *(const uint32_t*)(sm + RO_WHI + rb);
            whi[kt][1] = *(const uint32_t*)(sm + RO_WHI + rb + 8 * 560);
            whi[kt][2] = *(const uint32_t*)(sm + RO_WHI + rb + 16);
            whi[kt][3] = *(const uint32_t*)(sm + RO_WHI + rb + 8 * 560 + 16);
            wlo[kt][0] = *(const uint32_t*)(sm + RO_WLO + rb);
            wlo[kt][1] = *(const uint32_t*)(sm + RO_WLO + rb + 8 * 560);
            wlo[kt][2] = *(const uint32_t*)(sm + RO_WLO + rb + 16);
            wlo[kt][3] = *(const uint32_t*)(sm + RO_WLO + rb + 8 * 560 + 16);
        }
        __syncthreads();
    }
    grid_barrier(NB);   // h/c state globally visible

    for (int t = 0; t < TT; t++) {
        // ---- stage h slice [32 b][256 k] hi+lo into smem ----
        {
            int b = tid >> 3, q = tid & 7;
#pragma unroll
            for (int i = 0; i < 4; i++) {
                int ko = (i * 8 + q) * 8;
                *(uint4*)(sm + RO_HHI + b * 560 + ko * 2) =
                    *(const uint4*)(g_hbhi + (size_t)b * MM + k0 + ko);
                *(uint4*)(sm + RO_HLO + b * 560 + ko * 2) =
                    *(const uint4*)(g_hblo + (size_t)b * MM + k0 + ko);
            }
        }
        __syncthreads();

        // ---- HMMA: D[j][b] += W . h^T, 3-pass split ----
        float acc[4][4];
#pragma unroll
        for (int a = 0; a < 4; a++)
#pragma unroll
            for (int e = 0; e < 4; e++) acc[a][e] = 0.f;
#pragma unroll
        for (int kt = 0; kt < 16; kt++) {
            uint32_t bh[4][2], bl[4][2];
#pragma unroll
            for (int nt = 0; nt < 4; nt++) {
                int rb = (nt * 8 + g) * 560 + kt * 32 + 4 * tg;
                bh[nt][0] = *(const uint32_t*)(sm + RO_HHI + rb);
                bh[nt][1] = *(const uint32_t*)(sm + RO_HHI + rb + 16);
                bl[nt][0] = *(const uint32_t*)(sm + RO_HLO + rb);
                bl[nt][1] = *(const uint32_t*)(sm + RO_HLO + rb + 16);
            }
#pragma unroll
            for (int nt = 0; nt < 4; nt++) {
                mma16816(acc[nt], whi[kt], bh[nt]);
                mma16816(acc[nt], whi[kt], bl[nt]);
                mma16816(acc[nt], wlo[kt], bh[nt]);
            }
        }

        // ---- scatter partials to g_part[ks*32+b][j] ----
#pragma unroll
        for (int nt = 0; nt < 4; nt++) {
            int j = j0 + w * 16 + g;
            int b = nt * 8 + 2 * tg;
            g_part[(size_t)(ks * 32 + b) * G4 + j]         = acc[nt][0];
            g_part[(size_t)(ks * 32 + b + 1) * G4 + j]     = acc[nt][1];
            g_part[(size_t)(ks * 32 + b) * G4 + j + 8]     = acc[nt][2];
            g_part[(size_t)(ks * 32 + b + 1) * G4 + j + 8] = acc[nt][3];
        }
        grid_barrier(NB);

        // ---- cell update: one (b,m) per thread ----
        {
            int gi = bid * 256 + tid;
            int m = gi & 1023, b = gi >> 10;
            float vi = 0.f, vf = 0.f, vg = 0.f, vo = 0.f;
#pragma unroll
            for (int q = 0; q < 4; q++) {
                const float* p = g_part + (size_t)(q * 32 + b) * G4;
                vi += p[m]; vf += p[m + 1024]; vg += p[m + 2048]; vo += p[m + 3072];
            }
            const float* Gr = g_G + ((size_t)b * TT + t) * G4;
            vi += Gr[m] + bs[m];
            vf += Gr[m + 1024] + bs[m + 1024];
            vg += Gr[m + 2048] + bs[m + 2048];
            vo += Gr[m + 3072] + bs[m + 3072];
            float cp = g_c[gi];
            float iv = fast_sigmoid(vi), fv = fast_sigmoid(vf), ov = fast_sigmoid(vo);
            float gv = fast_tanh(vg);
            float cn = fv * cp + iv * gv;
            float hn = ov * fast_tanh(cn);
            g_c[gi] = cn;
            __nv_bfloat16 hhi = __float2bfloat16(hn);
            __nv_bfloat16 hlo = __float2bfloat16(hn - __bfloat162float(hhi));
            g_hbhi[gi] = hhi;
            g_hblo[gi] = hlo;
            size_t oidx = ((size_t)b * TT + t) * MM + m;
            if (layer == 0) { g_H0hi[oidx] = hhi; g_H0lo[oidx] = hlo; }
            else            { dout[oidx] = hn; }
            if (t == TT - 1) { hf[gi] = hn; cf[gi] = cn; }
        }
        grid_barrier(NB);
    }
}

// ---------------------------- launch ----------------------------------------
extern "C" void kernel_launch(void* const* d_in, const int* in_sizes, int n_in,
                              void* d_out, int out_size) {
    const float* x   = (const float*)d_in[0];
    const float* h   = (const float*)d_in[1];
    const float* c   = (const float*)d_in[2];
    const float* Wih = (const float*)d_in[3];
    const float* Whh = (const float*)d_in[4];
    const float* bih = (const float*)d_in[5];
    const float* bhh = (const float*)d_in[6];
    float* out = (float*)d_out;

    cudaFuncSetAttribute(igemm_kernel, cudaFuncAttributeMaxDynamicSharedMemorySize, IG_SMEM);
    cudaFuncSetAttribute(recur_kernel, cudaFuncAttributeMaxDynamicSharedMemorySize, RC_SMEM);

    prep_kernel<<<(unsigned)(((size_t)RR * NN) / 256), 256>>>(x, Wih, Whh, bih, bhh);

    igemm_kernel<<<dim3(RR / 128, G4 / 128), 256, IG_SMEM>>>(0, 0);
    recur_kernel<<<128, 256, RC_SMEM>>>(0, h, c, out);
    igemm_kernel<<<dim3(RR / 128, G4 / 128), 256, IG_SMEM>>>(1, 1);
    recur_kernel<<<128, 256, RC_SMEM>>>(1, h, c, out);
}